// round 1
// baseline (speedup 1.0000x reference)
#include <cuda_runtime.h>
#include <math.h>

// Problem constants
#define BATCH   65536
#define D_DIM   256
#define W_DIM   1024
#define TB      64        // rows per block
#define TW      64        // W-columns per chunk
#define NCHUNK  (W_DIM / TW)

// SMEM row strides (floats), chosen for bank-conflict-free inner loops
#define SZ_S  260   // sZ  [64][260]  (pad 4 keeps float4 STS aligned, a-loads 1-phase)
#define SW_S  257   // sW1 [64][257]  (b-loads 1-phase with interleaved cols)
#define SH_S  65    // sH  [64][65]
#define SV_S  257   // sW2t[64][257]  ([jj][i])

// float offsets in dynamic smem
#define OFF_Z   0
#define OFF_W1  (OFF_Z  + TB * SZ_S)
#define OFF_W2  (OFF_W1 + TW * SW_S)
#define OFF_H   (OFF_W2 + TW * SV_S)
#define OFF_TR  (OFF_H  + TB * SH_S)
#define SMEM_FLOATS (OFF_TR + TB)
#define SMEM_BYTES  (SMEM_FLOATS * 4)

__device__ float g_M[W_DIM];

// ---------------------------------------------------------------------------
// M[j] = sum_i W1[j,i] * W2[i,j]
// ---------------------------------------------------------------------------
__global__ void compute_M_kernel(const float* __restrict__ W1,
                                 const float* __restrict__ W2) {
    int j = blockIdx.x;          // 0..1023
    int i = threadIdx.x;         // 0..255
    float v = W1[j * D_DIM + i] * W2[(size_t)i * W_DIM + j];
    #pragma unroll
    for (int o = 16; o > 0; o >>= 1)
        v += __shfl_down_sync(0xffffffffu, v, o);
    __shared__ float red[8];
    if ((i & 31) == 0) red[i >> 5] = v;
    __syncthreads();
    if (i < 8) {
        float s = red[i];
        #pragma unroll
        for (int o = 4; o > 0; o >>= 1)
            s += __shfl_down_sync(0xffu, s, o);
        if (i == 0) g_M[j] = s;
    }
}

// ---------------------------------------------------------------------------
// Fused: pre = z@W1^T + b1 ; h = softplus(pre) ; dz = h@W2^T ;
//        trace = sigmoid(pre)@M ; dlogpz = -trace
// ---------------------------------------------------------------------------
__global__ void __launch_bounds__(256, 1)
planar_flow_kernel(const float* __restrict__ z,
                   const float* __restrict__ W1,
                   const float* __restrict__ b1,
                   const float* __restrict__ W2,
                   float* __restrict__ dz_out,
                   float* __restrict__ dlog_out) {
    extern __shared__ float smem[];
    float* sZ   = smem + OFF_Z;
    float* sW1  = smem + OFF_W1;
    float* sW2t = smem + OFF_W2;
    float* sH   = smem + OFF_H;
    float* sTr  = smem + OFF_TR;

    const int tid = threadIdx.x;        // 0..255
    const int tx  = tid & 15;           // 0..15
    const int ty  = tid >> 4;           // 0..15
    const int row0 = blockIdx.x * TB;

    // ---- stage z tile [64 x 256] -> sZ (float4, conflict-free) ----
    {
        const float4* z4 = reinterpret_cast<const float4*>(z + (size_t)row0 * D_DIM);
        for (int idx = tid; idx < TB * 64; idx += 256) {
            int r  = idx >> 6;
            int kq = idx & 63;
            float4 v = z4[r * 64 + kq];
            *reinterpret_cast<float4*>(sZ + r * SZ_S + kq * 4) = v;
        }
        if (tid < TB) sTr[tid] = 0.0f;
    }

    // persistent accumulators
    float dz[4][16];
    #pragma unroll
    for (int q = 0; q < 4; q++)
        #pragma unroll
        for (int p = 0; p < 16; p++)
            dz[q][p] = 0.0f;
    float tr[4] = {0.f, 0.f, 0.f, 0.f};

    for (int ch = 0; ch < NCHUNK; ch++) {
        const int jc = ch * TW;
        __syncthreads();   // protect sW1/sW2t/sH from previous iteration readers

        // ---- stage W1 chunk [64 x 256] -> sW1 (rows = local j, stride 257) ----
        for (int idx = tid; idx < TW * 64; idx += 256) {
            int c  = idx >> 6;
            int kq = idx & 63;
            float4 v = *reinterpret_cast<const float4*>(
                W1 + (size_t)(jc + c) * D_DIM + kq * 4);
            float* dst = sW1 + c * SW_S + kq * 4;
            dst[0] = v.x; dst[1] = v.y; dst[2] = v.z; dst[3] = v.w;
        }
        // ---- stage W2 chunk transposed: sW2t[jj][i] = W2[i][jc+jj] ----
        for (int idx = tid; idx < D_DIM * 16; idx += 256) {
            int i  = idx >> 4;
            int jq = idx & 15;
            float4 v = *reinterpret_cast<const float4*>(
                W2 + (size_t)i * W_DIM + jc + jq * 4);
            sW2t[(jq * 4 + 0) * SV_S + i] = v.x;
            sW2t[(jq * 4 + 1) * SV_S + i] = v.y;
            sW2t[(jq * 4 + 2) * SV_S + i] = v.z;
            sW2t[(jq * 4 + 3) * SV_S + i] = v.w;
        }
        __syncthreads();

        // ---- GEMM1: pre[64x64] = sZ[64x256] * sW1[64x256]^T ----
        // thread microtile: rows {ty+16q}, cols {tx+16p}
        float pre[4][4];
        #pragma unroll
        for (int q = 0; q < 4; q++)
            #pragma unroll
            for (int p = 0; p < 4; p++)
                pre[q][p] = 0.0f;

        #pragma unroll 4
        for (int k = 0; k < D_DIM; k++) {
            float a[4], b[4];
            #pragma unroll
            for (int q = 0; q < 4; q++) a[q] = sZ[(ty + 16 * q) * SZ_S + k];
            #pragma unroll
            for (int p = 0; p < 4; p++) b[p] = sW1[(tx + 16 * p) * SW_S + k];
            #pragma unroll
            for (int q = 0; q < 4; q++)
                #pragma unroll
                for (int p = 0; p < 4; p++)
                    pre[q][p] = fmaf(a[q], b[p], pre[q][p]);
        }

        // ---- epilogue: softplus -> sH, sigmoid*M -> trace ----
        float b1v[4], Mv[4];
        #pragma unroll
        for (int p = 0; p < 4; p++) {
            b1v[p] = b1[jc + tx + 16 * p];
            Mv[p]  = g_M[jc + tx + 16 * p];
        }
        #pragma unroll
        for (int q = 0; q < 4; q++) {
            #pragma unroll
            for (int p = 0; p < 4; p++) {
                float x = pre[q][p] + b1v[p];
                // softplus(x) = max(x,0) + log1p(exp(-|x|))  (stable, matches jax)
                float e  = __expf(-fabsf(x));
                float sp = fmaxf(x, 0.0f) + log1pf(e);
                // sigmoid(x): x>=0: 1/(1+e) ; x<0: e/(1+e)
                float inv = 1.0f / (1.0f + e);
                float sg  = (x >= 0.0f) ? inv : e * inv;
                sH[(ty + 16 * q) * SH_S + (tx + 16 * p)] = sp;
                tr[q] = fmaf(sg, Mv[p], tr[q]);
            }
        }
        __syncthreads();

        // ---- GEMM2: dz[64x256] += sH[64x64] * sW2t[64x256] ----
        // thread microtile: rows {ty+16q}, cols {tx+16p}, p=0..15
        #pragma unroll 2
        for (int jj = 0; jj < TW; jj++) {
            float a[4];
            #pragma unroll
            for (int q = 0; q < 4; q++) a[q] = sH[(ty + 16 * q) * SH_S + jj];
            float bvec[16];
            #pragma unroll
            for (int p = 0; p < 16; p++) bvec[p] = sW2t[jj * SV_S + tx + 16 * p];
            #pragma unroll
            for (int q = 0; q < 4; q++)
                #pragma unroll
                for (int p = 0; p < 16; p++)
                    dz[q][p] = fmaf(a[q], bvec[p], dz[q][p]);
        }
    }

    // ---- write dz ----
    #pragma unroll
    for (int q = 0; q < 4; q++) {
        int r = row0 + ty + 16 * q;
        #pragma unroll
        for (int p = 0; p < 16; p++)
            dz_out[(size_t)r * D_DIM + tx + 16 * p] = dz[q][p];
    }

    // ---- reduce trace across tx and write dlogpz ----
    #pragma unroll
    for (int q = 0; q < 4; q++)
        atomicAdd(&sTr[ty + 16 * q], tr[q]);
    __syncthreads();
    if (tid < TB)
        dlog_out[row0 + tid] = -sTr[tid];
}

// ---------------------------------------------------------------------------
extern "C" void kernel_launch(void* const* d_in, const int* in_sizes, int n_in,
                              void* d_out, int out_size) {
    // inputs: t, z, W1, b1, W2
    const float* z  = (const float*)d_in[1];
    const float* W1 = (const float*)d_in[2];
    const float* b1 = (const float*)d_in[3];
    const float* W2 = (const float*)d_in[4];

    float* dz   = (float*)d_out;                      // [B, D]
    float* dlog = dz + (size_t)BATCH * D_DIM;         // [B, 1]

    compute_M_kernel<<<W_DIM, 256>>>(W1, W2);

    cudaFuncSetAttribute(planar_flow_kernel,
                         cudaFuncAttributeMaxDynamicSharedMemorySize, SMEM_BYTES);
    planar_flow_kernel<<<BATCH / TB, 256, SMEM_BYTES>>>(z, W1, b1, W2, dz, dlog);
}

// round 2
// speedup vs baseline: 1.0010x; 1.0010x over previous
#include <cuda_runtime.h>
#include <math.h>

// Problem constants
#define BATCH   65536
#define D_DIM   256
#define W_DIM   1024
#define TB      64        // rows per block
#define TW      64        // W-columns per chunk
#define NCHUNK  (W_DIM / TW)

// SMEM row strides (floats), chosen for bank-conflict-free inner loops
#define SZ_S  260   // sZ  [64][260]  (pad 4 keeps float4 STS aligned, a-loads 1-phase)
#define SW_S  257   // sW1 [64][257]  (b-loads 1-phase with interleaved cols)
#define SH_S  65    // sH  [64][65]
#define SV_S  257   // sW2t[64][257]  ([jj][i])

// float offsets in dynamic smem
#define OFF_Z   0
#define OFF_W1  (OFF_Z  + TB * SZ_S)
#define OFF_W2  (OFF_W1 + TW * SW_S)
#define OFF_H   (OFF_W2 + TW * SV_S)
#define OFF_TR  (OFF_H  + TB * SH_S)
#define SMEM_FLOATS (OFF_TR + TB)
#define SMEM_BYTES  (SMEM_FLOATS * 4)

__device__ float g_M[W_DIM];

// ---------------------------------------------------------------------------
// M[j] = sum_i W1[j,i] * W2[i,j]
// ---------------------------------------------------------------------------
__global__ void compute_M_kernel(const float* __restrict__ W1,
                                 const float* __restrict__ W2) {
    int j = blockIdx.x;          // 0..1023
    int i = threadIdx.x;         // 0..255
    float v = W1[j * D_DIM + i] * W2[(size_t)i * W_DIM + j];
    #pragma unroll
    for (int o = 16; o > 0; o >>= 1)
        v += __shfl_down_sync(0xffffffffu, v, o);
    __shared__ float red[8];
    if ((i & 31) == 0) red[i >> 5] = v;
    __syncthreads();
    if (i < 8) {
        float s = red[i];
        #pragma unroll
        for (int o = 4; o > 0; o >>= 1)
            s += __shfl_down_sync(0xffu, s, o);
        if (i == 0) g_M[j] = s;
    }
}

// ---------------------------------------------------------------------------
// Fused: pre = z@W1^T + b1 ; h = softplus(pre) ; dz = h@W2^T ;
//        trace = sigmoid(pre)@M ; dlogpz = -trace
// ---------------------------------------------------------------------------
__global__ void __launch_bounds__(256, 1)
planar_flow_kernel(const float* __restrict__ z,
                   const float* __restrict__ W1,
                   const float* __restrict__ b1,
                   const float* __restrict__ W2,
                   float* __restrict__ dz_out,
                   float* __restrict__ dlog_out) {
    extern __shared__ float smem[];
    float* sZ   = smem + OFF_Z;
    float* sW1  = smem + OFF_W1;
    float* sW2t = smem + OFF_W2;
    float* sH   = smem + OFF_H;
    float* sTr  = smem + OFF_TR;

    const int tid = threadIdx.x;        // 0..255
    const int tx  = tid & 15;           // 0..15
    const int ty  = tid >> 4;           // 0..15
    const int row0 = blockIdx.x * TB;

    // ---- stage z tile [64 x 256] -> sZ (float4, conflict-free) ----
    {
        const float4* z4 = reinterpret_cast<const float4*>(z + (size_t)row0 * D_DIM);
        for (int idx = tid; idx < TB * 64; idx += 256) {
            int r  = idx >> 6;
            int kq = idx & 63;
            float4 v = z4[r * 64 + kq];
            *reinterpret_cast<float4*>(sZ + r * SZ_S + kq * 4) = v;
        }
        if (tid < TB) sTr[tid] = 0.0f;
    }

    // persistent accumulators
    float dz[4][16];
    #pragma unroll
    for (int q = 0; q < 4; q++)
        #pragma unroll
        for (int p = 0; p < 16; p++)
            dz[q][p] = 0.0f;
    float tr[4] = {0.f, 0.f, 0.f, 0.f};

    for (int ch = 0; ch < NCHUNK; ch++) {
        const int jc = ch * TW;
        __syncthreads();   // protect sW1/sW2t/sH from previous iteration readers

        // ---- stage W1 chunk [64 x 256] -> sW1 (rows = local j, stride 257) ----
        for (int idx = tid; idx < TW * 64; idx += 256) {
            int c  = idx >> 6;
            int kq = idx & 63;
            float4 v = *reinterpret_cast<const float4*>(
                W1 + (size_t)(jc + c) * D_DIM + kq * 4);
            float* dst = sW1 + c * SW_S + kq * 4;
            dst[0] = v.x; dst[1] = v.y; dst[2] = v.z; dst[3] = v.w;
        }
        // ---- stage W2 chunk transposed: sW2t[jj][i] = W2[i][jc+jj] ----
        for (int idx = tid; idx < D_DIM * 16; idx += 256) {
            int i  = idx >> 4;
            int jq = idx & 15;
            float4 v = *reinterpret_cast<const float4*>(
                W2 + (size_t)i * W_DIM + jc + jq * 4);
            sW2t[(jq * 4 + 0) * SV_S + i] = v.x;
            sW2t[(jq * 4 + 1) * SV_S + i] = v.y;
            sW2t[(jq * 4 + 2) * SV_S + i] = v.z;
            sW2t[(jq * 4 + 3) * SV_S + i] = v.w;
        }
        __syncthreads();

        // ---- GEMM1: pre[64x64] = sZ[64x256] * sW1[64x256]^T ----
        // thread microtile: rows {ty+16q}, cols {tx+16p}
        float pre[4][4];
        #pragma unroll
        for (int q = 0; q < 4; q++)
            #pragma unroll
            for (int p = 0; p < 4; p++)
                pre[q][p] = 0.0f;

        #pragma unroll 4
        for (int k = 0; k < D_DIM; k++) {
            float a[4], b[4];
            #pragma unroll
            for (int q = 0; q < 4; q++) a[q] = sZ[(ty + 16 * q) * SZ_S + k];
            #pragma unroll
            for (int p = 0; p < 4; p++) b[p] = sW1[(tx + 16 * p) * SW_S + k];
            #pragma unroll
            for (int q = 0; q < 4; q++)
                #pragma unroll
                for (int p = 0; p < 4; p++)
                    pre[q][p] = fmaf(a[q], b[p], pre[q][p]);
        }

        // ---- epilogue: softplus -> sH, sigmoid*M -> trace ----
        float b1v[4], Mv[4];
        #pragma unroll
        for (int p = 0; p < 4; p++) {
            b1v[p] = b1[jc + tx + 16 * p];
            Mv[p]  = g_M[jc + tx + 16 * p];
        }
        #pragma unroll
        for (int q = 0; q < 4; q++) {
            #pragma unroll
            for (int p = 0; p < 4; p++) {
                float x = pre[q][p] + b1v[p];
                // softplus(x) = max(x,0) + log1p(exp(-|x|))  (stable, matches jax)
                float e  = __expf(-fabsf(x));
                float sp = fmaxf(x, 0.0f) + log1pf(e);
                // sigmoid(x): x>=0: 1/(1+e) ; x<0: e/(1+e)
                float inv = 1.0f / (1.0f + e);
                float sg  = (x >= 0.0f) ? inv : e * inv;
                sH[(ty + 16 * q) * SH_S + (tx + 16 * p)] = sp;
                tr[q] = fmaf(sg, Mv[p], tr[q]);
            }
        }
        __syncthreads();

        // ---- GEMM2: dz[64x256] += sH[64x64] * sW2t[64x256] ----
        // thread microtile: rows {ty+16q}, cols {tx+16p}, p=0..15
        #pragma unroll 2
        for (int jj = 0; jj < TW; jj++) {
            float a[4];
            #pragma unroll
            for (int q = 0; q < 4; q++) a[q] = sH[(ty + 16 * q) * SH_S + jj];
            float bvec[16];
            #pragma unroll
            for (int p = 0; p < 16; p++) bvec[p] = sW2t[jj * SV_S + tx + 16 * p];
            #pragma unroll
            for (int q = 0; q < 4; q++)
                #pragma unroll
                for (int p = 0; p < 16; p++)
                    dz[q][p] = fmaf(a[q], bvec[p], dz[q][p]);
        }
    }

    // ---- write dz ----
    #pragma unroll
    for (int q = 0; q < 4; q++) {
        int r = row0 + ty + 16 * q;
        #pragma unroll
        for (int p = 0; p < 16; p++)
            dz_out[(size_t)r * D_DIM + tx + 16 * p] = dz[q][p];
    }

    // ---- reduce trace across tx and write dlogpz ----
    #pragma unroll
    for (int q = 0; q < 4; q++)
        atomicAdd(&sTr[ty + 16 * q], tr[q]);
    __syncthreads();
    if (tid < TB)
        dlog_out[row0 + tid] = -sTr[tid];
}

// ---------------------------------------------------------------------------
extern "C" void kernel_launch(void* const* d_in, const int* in_sizes, int n_in,
                              void* d_out, int out_size) {
    // inputs: t, z, W1, b1, W2
    const float* z  = (const float*)d_in[1];
    const float* W1 = (const float*)d_in[2];
    const float* b1 = (const float*)d_in[3];
    const float* W2 = (const float*)d_in[4];

    float* dz   = (float*)d_out;                      // [B, D]
    float* dlog = dz + (size_t)BATCH * D_DIM;         // [B, 1]

    compute_M_kernel<<<W_DIM, 256>>>(W1, W2);

    cudaFuncSetAttribute(planar_flow_kernel,
                         cudaFuncAttributeMaxDynamicSharedMemorySize, SMEM_BYTES);
    planar_flow_kernel<<<BATCH / TB, 256, SMEM_BYTES>>>(z, W1, b1, W2, dz, dlog);
}

// round 4
// speedup vs baseline: 3.1237x; 3.1205x over previous
#include <cuda_runtime.h>
#include <cuda_bf16.h>
#include <stdint.h>
#include <math.h>

#define BATCH  65536
#define D_DIM  256
#define W_DIM  1024
#define MTILE  64
#define CW     64
#define NCHUNK (W_DIM / CW)    // 16

// bf16 hi/lo split images (natural row-major) in device scratch
__device__ __align__(16) __nv_bfloat16 g_z_hi[(size_t)BATCH * D_DIM];
__device__ __align__(16) __nv_bfloat16 g_z_lo[(size_t)BATCH * D_DIM];
__device__ __align__(16) __nv_bfloat16 g_w1_hi[W_DIM * D_DIM];
__device__ __align__(16) __nv_bfloat16 g_w1_lo[W_DIM * D_DIM];
__device__ __align__(16) __nv_bfloat16 g_w2_hi[D_DIM * W_DIM];
__device__ __align__(16) __nv_bfloat16 g_w2_lo[D_DIM * W_DIM];
__device__ float g_M[W_DIM];

// ---------------- SMEM layout (bytes) ----------------
// z  : [64][264] bf16, stride 528B (odd multiple of 16B -> conflict-free ldmatrix)
// W1 : [64][264] bf16 (chunk, rows = W-col j, cols = k)
// W2 : [256][72] bf16, stride 144B (rows = out i, cols = chunk j)
// h  : [64][72]  bf16
#define Z_HI   0
#define Z_LO   33792
#define W1_HI  67584
#define W1_LO  101376
#define W2_HI  135168
#define W2_LO  172032
#define H_HI   208896
#define H_LO   218112
#define TR_OFF 227328
#define S_TOTAL 227584

#define ZS  528
#define W2S 144
#define HS  144
#define DLO 33792      // hi->lo offset for z / W1
#define DW2 36864      // hi->lo offset for W2
#define DH  9216       // hi->lo offset for h

// ---------------- PTX helpers ----------------
__device__ __forceinline__ uint32_t smem_u32(const void* p) {
    uint32_t a;
    asm("{ .reg .u64 t; cvta.to.shared.u64 t, %1; cvt.u32.u64 %0, t; }" : "=r"(a) : "l"(p));
    return a;
}
#define CP_ASYNC16(d, s) \
    asm volatile("cp.async.cg.shared.global [%0], [%1], 16;" :: "r"(d), "l"(s))
#define CP_COMMIT() asm volatile("cp.async.commit_group;")
#define CP_WAIT0()  asm volatile("cp.async.wait_group 0;")
#define CP_WAIT1()  asm volatile("cp.async.wait_group 1;")

#define LDSM4(r, addr) \
    asm volatile("ldmatrix.sync.aligned.m8n8.x4.shared.b16 {%0,%1,%2,%3}, [%4];" \
        : "=r"((r)[0]), "=r"((r)[1]), "=r"((r)[2]), "=r"((r)[3]) : "r"(addr))

__device__ __forceinline__ void mma_bf16(float* c, const uint32_t* a, uint32_t b0, uint32_t b1) {
    asm volatile(
        "mma.sync.aligned.m16n8k16.row.col.f32.bf16.bf16.f32 "
        "{%0,%1,%2,%3}, {%4,%5,%6,%7}, {%8,%9}, {%0,%1,%2,%3};"
        : "+f"(c[0]), "+f"(c[1]), "+f"(c[2]), "+f"(c[3])
        : "r"(a[0]), "r"(a[1]), "r"(a[2]), "r"(a[3]), "r"(b0), "r"(b1));
}

// ---------------- split pre-pass ----------------
union Pack8 { uint4 u; __nv_bfloat16 b[8]; };

__device__ __forceinline__ uint4 split8_hi(const float* v, Pack8& lo) {
    Pack8 hi;
    #pragma unroll
    for (int i = 0; i < 8; i++) {
        __nv_bfloat16 h = __float2bfloat16_rn(v[i]);
        hi.b[i] = h;
        lo.b[i] = __float2bfloat16_rn(v[i] - __bfloat162float(h));
    }
    return hi.u;
}

__global__ void split_kernel(const float* __restrict__ src,
                             __nv_bfloat16* __restrict__ dhi,
                             __nv_bfloat16* __restrict__ dlo) {
    size_t gid = (size_t)blockIdx.x * 256 + threadIdx.x;   // 8 floats per thread
    const float4* s = reinterpret_cast<const float4*>(src);
    float4 a = s[gid * 2], b = s[gid * 2 + 1];
    float v[8] = {a.x, a.y, a.z, a.w, b.x, b.y, b.z, b.w};
    Pack8 lo;
    uint4 hi = split8_hi(v, lo);
    reinterpret_cast<uint4*>(dhi)[gid] = hi;
    reinterpret_cast<uint4*>(dlo)[gid] = lo.u;
}

__global__ void compute_M_kernel(const float* __restrict__ W1, const float* __restrict__ W2) {
    int j = blockIdx.x, i = threadIdx.x;
    float v = W1[j * D_DIM + i] * W2[(size_t)i * W_DIM + j];
    #pragma unroll
    for (int o = 16; o > 0; o >>= 1) v += __shfl_down_sync(0xffffffffu, v, o);
    __shared__ float red[8];
    if ((i & 31) == 0) red[i >> 5] = v;
    __syncthreads();
    if (i < 8) {
        float s = red[i];
        #pragma unroll
        for (int o = 4; o > 0; o >>= 1) s += __shfl_down_sync(0xffu, s, o);
        if (i == 0) g_M[j] = s;
    }
}

// ---------------- copy helpers (cp.async) ----------------
// rows x 256 bf16 from natural layout -> smem stride 528B
__device__ __forceinline__ void cp_tile256(uint32_t sdst, const __nv_bfloat16* g, int rows) {
    int total = rows * 32;
    for (int i = threadIdx.x; i < total; i += 256) {
        int r = i >> 5, c = i & 31;
        CP_ASYNC16(sdst + r * ZS + c * 16, g + r * 256 + c * 8);
    }
}
// 256 rows x 64 bf16 from stride-1024 rows -> smem stride 144B
__device__ __forceinline__ void cp_tileW2(uint32_t sdst, const __nv_bfloat16* g) {
    for (int i = threadIdx.x; i < 256 * 8; i += 256) {
        int r = i >> 3, c = i & 7;
        CP_ASYNC16(sdst + r * W2S + c * 16, g + (size_t)r * W_DIM + c * 8);
    }
}

// ---------------- main fused kernel ----------------
__global__ void __launch_bounds__(256, 1)
planar_mma_kernel(const float* __restrict__ b1,
                  float* __restrict__ dz_out,
                  float* __restrict__ dlog_out) {
    extern __shared__ char smem[];
    const uint32_t sb = smem_u32(smem);
    float* sTr = reinterpret_cast<float*>(smem + TR_OFF);

    const int tid  = threadIdx.x;
    const int wid  = tid >> 5;
    const int lane = tid & 31;
    const int mg   = wid >> 2;     // 0/1 : rows 32*mg .. +31
    const int ng   = wid & 3;      // GEMM1 n-group (16 cols), GEMM2 n-group (64 cols)
    const int row0 = blockIdx.x * MTILE;

    if (tid < MTILE) sTr[tid] = 0.0f;

    // stage z (hi+lo) + chunk 0 weights
    cp_tile256(sb + Z_HI, g_z_hi + (size_t)row0 * D_DIM, 64);
    cp_tile256(sb + Z_LO, g_z_lo + (size_t)row0 * D_DIM, 64);
    cp_tile256(sb + W1_HI, g_w1_hi, 64);
    cp_tile256(sb + W1_LO, g_w1_lo, 64);
    cp_tileW2(sb + W2_HI, g_w2_hi);
    cp_tileW2(sb + W2_LO, g_w2_lo);
    CP_COMMIT();
    CP_WAIT0();
    __syncthreads();

    // per-lane ldmatrix base addresses
    const int lrow16 = lane & 15;          // A-frag row within 16
    const int lkhalf = (lane >> 4) << 3;   // A-frag k half (0/8)
    const int brow   = (lane & 7) + ((lane >> 4) << 3);   // B-frag row within 16
    const int bkhalf = ((lane >> 3) & 1) << 3;            // B-frag k half

    const uint32_t aZ0 = sb + Z_HI + (mg * 32 + lrow16) * ZS + lkhalf * 2;
    const uint32_t aZ1 = aZ0 + 16 * ZS;
    const uint32_t bW1 = sb + W1_HI + (ng * 16 + brow) * ZS + bkhalf * 2;
    const uint32_t aH0 = sb + H_HI + (mg * 32 + lrow16) * HS + lkhalf * 2;
    const uint32_t aH1 = aH0 + 16 * HS;
    uint32_t bW2[4];
    #pragma unroll
    for (int t = 0; t < 4; t++)
        bW2[t] = sb + W2_HI + (ng * 64 + t * 16 + brow) * W2S + bkhalf * 2;

    float dz[2][8][4];
    #pragma unroll
    for (int a = 0; a < 2; a++)
        #pragma unroll
        for (int b = 0; b < 8; b++)
            #pragma unroll
            for (int c = 0; c < 4; c++) dz[a][b][c] = 0.0f;
    float tr4[4] = {0.f, 0.f, 0.f, 0.f};

    for (int ch = 0; ch < NCHUNK; ch++) {
        const int jc = ch * CW;

        // ---------------- GEMM1: pre[64x64] = z @ W1chunk^T (3 bf16 terms) ----
        float pre[2][2][4];
        #pragma unroll
        for (int a = 0; a < 2; a++)
            #pragma unroll
            for (int b = 0; b < 2; b++)
                #pragma unroll
                for (int c = 0; c < 4; c++) pre[a][b][c] = 0.0f;

        #pragma unroll 4
        for (int ks = 0; ks < 16; ks++) {
            const int kb = ks * 32;
            uint32_t ah0[4], ah1[4], al0[4], al1[4], bh[4], bl[4];
            LDSM4(ah0, aZ0 + kb);
            LDSM4(ah1, aZ1 + kb);
            LDSM4(al0, aZ0 + kb + DLO);
            LDSM4(al1, aZ1 + kb + DLO);
            LDSM4(bh,  bW1 + kb);
            LDSM4(bl,  bW1 + kb + DLO);
            // hi*hi
            mma_bf16(pre[0][0], ah0, bh[0], bh[1]);
            mma_bf16(pre[0][1], ah0, bh[2], bh[3]);
            mma_bf16(pre[1][0], ah1, bh[0], bh[1]);
            mma_bf16(pre[1][1], ah1, bh[2], bh[3]);
            // lo*hi
            mma_bf16(pre[0][0], al0, bh[0], bh[1]);
            mma_bf16(pre[0][1], al0, bh[2], bh[3]);
            mma_bf16(pre[1][0], al1, bh[0], bh[1]);
            mma_bf16(pre[1][1], al1, bh[2], bh[3]);
            // hi*lo
            mma_bf16(pre[0][0], ah0, bl[0], bl[1]);
            mma_bf16(pre[0][1], ah0, bl[2], bl[3]);
            mma_bf16(pre[1][0], ah1, bl[0], bl[1]);
            mma_bf16(pre[1][1], ah1, bl[2], bl[3]);
        }

        // ---------------- epilogue: softplus -> h (hi/lo), sigmoid*M -> trace --
        #pragma unroll
        for (int mf = 0; mf < 2; mf++) {
            #pragma unroll
            for (int nf = 0; nf < 2; nf++) {
                const int j0 = jc + ng * 16 + nf * 8 + 2 * (lane & 3);
                const float b10 = __ldg(&b1[j0]),   b11 = __ldg(&b1[j0 + 1]);
                const float M0  = g_M[j0],          M1  = g_M[j0 + 1];
                #pragma unroll
                for (int bq = 0; bq < 2; bq++) {
                    float x0 = pre[mf][nf][2 * bq]     + b10;
                    float x1 = pre[mf][nf][2 * bq + 1] + b11;
                    float e0 = __expf(-fabsf(x0)), e1 = __expf(-fabsf(x1));
                    float sp0 = fmaxf(x0, 0.0f) + __logf(1.0f + e0);
                    float sp1 = fmaxf(x1, 0.0f) + __logf(1.0f + e1);
                    float i0 = __fdividef(1.0f, 1.0f + e0);
                    float i1 = __fdividef(1.0f, 1.0f + e1);
                    float sg0 = (x0 >= 0.0f) ? i0 : e0 * i0;
                    float sg1 = (x1 >= 0.0f) ? i1 : e1 * i1;
                    tr4[mf * 2 + bq] = fmaf(sg0, M0, tr4[mf * 2 + bq]);
                    tr4[mf * 2 + bq] = fmaf(sg1, M1, tr4[mf * 2 + bq]);
                    __nv_bfloat16 h0 = __float2bfloat16_rn(sp0);
                    __nv_bfloat16 h1 = __float2bfloat16_rn(sp1);
                    uint32_t phi = ((uint32_t)__bfloat16_as_ushort(h1) << 16) |
                                   (uint32_t)__bfloat16_as_ushort(h0);
                    __nv_bfloat16 l0 = __float2bfloat16_rn(sp0 - __bfloat162float(h0));
                    __nv_bfloat16 l1 = __float2bfloat16_rn(sp1 - __bfloat162float(h1));
                    uint32_t plo = ((uint32_t)__bfloat16_as_ushort(l1) << 16) |
                                   (uint32_t)__bfloat16_as_ushort(l0);
                    const int rl = mg * 32 + mf * 16 + (lane >> 2) + 8 * bq;
                    const int cl = ng * 16 + nf * 8 + 2 * (lane & 3);
                    const uint32_t ha = sb + H_HI + rl * HS + cl * 2;
                    asm volatile("st.shared.b32 [%0], %1;" :: "r"(ha), "r"(phi) : "memory");
                    asm volatile("st.shared.b32 [%0], %1;" :: "r"(ha + DH), "r"(plo) : "memory");
                }
            }
        }
        __syncthreads();   // h visible to all; every warp past GEMM1 -> W1 free

        // prefetch next W1 (hidden under GEMM2)
        if (ch + 1 < NCHUNK) {
            cp_tile256(sb + W1_HI, g_w1_hi + (size_t)(jc + CW) * D_DIM, 64);
            cp_tile256(sb + W1_LO, g_w1_lo + (size_t)(jc + CW) * D_DIM, 64);
            CP_COMMIT();
        }

        // ---------------- GEMM2: dz[64x256] += h @ W2chunk (3 bf16 terms) -----
        #pragma unroll
        for (int ks = 0; ks < 4; ks++) {
            const int kb = ks * 32;
            uint32_t ah0[4], ah1[4], al0[4], al1[4];
            LDSM4(ah0, aH0 + kb);
            LDSM4(ah1, aH1 + kb);
            LDSM4(al0, aH0 + kb + DH);
            LDSM4(al1, aH1 + kb + DH);
            #pragma unroll
            for (int t = 0; t < 4; t++) {
                uint32_t bh[4], bl[4];
                LDSM4(bh, bW2[t] + kb);
                LDSM4(bl, bW2[t] + kb + DW2);
                // hi*hi
                mma_bf16(dz[0][2 * t],     ah0, bh[0], bh[1]);
                mma_bf16(dz[0][2 * t + 1], ah0, bh[2], bh[3]);
                mma_bf16(dz[1][2 * t],     ah1, bh[0], bh[1]);
                mma_bf16(dz[1][2 * t + 1], ah1, bh[2], bh[3]);
                // lo*hi
                mma_bf16(dz[0][2 * t],     al0, bh[0], bh[1]);
                mma_bf16(dz[0][2 * t + 1], al0, bh[2], bh[3]);
                mma_bf16(dz[1][2 * t],     al1, bh[0], bh[1]);
                mma_bf16(dz[1][2 * t + 1], al1, bh[2], bh[3]);
                // hi*lo
                mma_bf16(dz[0][2 * t],     ah0, bl[0], bl[1]);
                mma_bf16(dz[0][2 * t + 1], ah0, bl[2], bl[3]);
                mma_bf16(dz[1][2 * t],     ah1, bl[0], bl[1]);
                mma_bf16(dz[1][2 * t + 1], ah1, bl[2], bl[3]);
            }
        }
        __syncthreads();   // all warps done with W2 + h

        // prefetch next W2, then wait for both W1+W2 of next chunk
        if (ch + 1 < NCHUNK) {
            cp_tileW2(sb + W2_HI, g_w2_hi + jc + CW);
            cp_tileW2(sb + W2_LO, g_w2_lo + jc + CW);
            CP_COMMIT();
            CP_WAIT0();
            __syncthreads();
        }
    }

    // ---------------- writeout ----------------
    #pragma unroll
    for (int mf = 0; mf < 2; mf++) {
        const int rl = mg * 32 + mf * 16 + (lane >> 2);
        #pragma unroll
        for (int nf = 0; nf < 8; nf++) {
            const int col = ng * 64 + nf * 8 + 2 * (lane & 3);
            float2 v0 = make_float2(dz[mf][nf][0], dz[mf][nf][1]);
            float2 v1 = make_float2(dz[mf][nf][2], dz[mf][nf][3]);
            *reinterpret_cast<float2*>(dz_out + (size_t)(row0 + rl) * D_DIM + col) = v0;
            *reinterpret_cast<float2*>(dz_out + (size_t)(row0 + rl + 8) * D_DIM + col) = v1;
        }
    }
    #pragma unroll
    for (int i = 0; i < 4; i++) {
        const int rl = mg * 32 + (i >> 1) * 16 + (lane >> 2) + 8 * (i & 1);
        atomicAdd(&sTr[rl], tr4[i]);
    }
    __syncthreads();
    if (tid < MTILE) dlog_out[row0 + tid] = -sTr[tid];
}

// ---------------------------------------------------------------------------
extern "C" void kernel_launch(void* const* d_in, const int* in_sizes, int n_in,
                              void* d_out, int out_size) {
    const float* z  = (const float*)d_in[1];
    const float* W1 = (const float*)d_in[2];
    const float* b1 = (const float*)d_in[3];
    const float* W2 = (const float*)d_in[4];

    float* dz   = (float*)d_out;
    float* dlog = dz + (size_t)BATCH * D_DIM;

    __nv_bfloat16 *zhi, *zlo, *w1hi, *w1lo, *w2hi, *w2lo;
    cudaGetSymbolAddress((void**)&zhi,  g_z_hi);
    cudaGetSymbolAddress((void**)&zlo,  g_z_lo);
    cudaGetSymbolAddress((void**)&w1hi, g_w1_hi);
    cudaGetSymbolAddress((void**)&w1lo, g_w1_lo);
    cudaGetSymbolAddress((void**)&w2hi, g_w2_hi);
    cudaGetSymbolAddress((void**)&w2lo, g_w2_lo);

    split_kernel<<<(int)((size_t)BATCH * D_DIM / 8 / 256), 256>>>(z, zhi, zlo);
    split_kernel<<<(W_DIM * D_DIM / 8) / 256, 256>>>(W1, w1hi, w1lo);
    split_kernel<<<(D_DIM * W_DIM / 8) / 256, 256>>>(W2, w2hi, w2lo);
    compute_M_kernel<<<W_DIM, 256>>>(W1, W2);

    cudaFuncSetAttribute(planar_mma_kernel,
                         cudaFuncAttributeMaxDynamicSharedMemorySize, S_TOTAL);
    planar_mma_kernel<<<BATCH / MTILE, 256, S_TOTAL>>>(b1, dz, dlog);
}